// round 13
// baseline (speedup 1.0000x reference)
#include <cuda_runtime.h>

// DotAttention: rnn_out [S,B,H] f32, state [2,2,B,H/2] f32 -> out [B,H,1] f32
// S=2048, B=32, H=1024.
// pass1: flash-style online-softmax partials. CTA = 8 warps mapped to 8
//        CONSECUTIVE batches at the same s-chunk -> each loop iteration the
//        CTA reads a contiguous 32KB block (DRAM row-buffer locality).
//        Per-warp partials (2048), register mrg, no smem/syncs.
// pass2: fused combine (M/L) + weighted sum over 64 partials/batch (R5 shape).

#define S_LEN 2048
#define B_DIM 32
#define H_DIM 1024
#define SPLIT 64
#define CHUNK (S_LEN / SPLIT)          // 32 rows per warp
#define NPART (B_DIM * SPLIT)          // 2048 partials

__device__ float g_m[NPART];
__device__ float g_l[NPART];
__device__ float g_acc[(size_t)NPART * H_DIM];   // 8.4 MB scratch (L2-resident)

__global__ __launch_bounds__(256) void pass1(const float* __restrict__ rnn,
                                             const float* __restrict__ state) {
    const int lane = threadIdx.x & 31;
    const int wid  = threadIdx.x >> 5;           // 0..7
    const int grp   = blockIdx.x >> 6;           // 0..3  batch group
    const int chunk = blockIdx.x & 63;           // 0..63 shared by all warps
    const int b     = grp * 8 + wid;             // warp's batch

    // merged[b, h]: h = j*128 + lane*4; direction = h>>9
    float4 mrg[8];
#pragma unroll
    for (int j = 0; j < 8; j++) {
        int h = j * 128 + lane * 4;
        int d = h >> 9;
        int hh = h & 511;
        mrg[j] = *reinterpret_cast<const float4*>(
            state + (size_t)(2 + d) * B_DIM * 512 + (size_t)b * 512 + hh);
    }

    float4 acc[8];
#pragma unroll
    for (int j = 0; j < 8; j++) acc[j] = make_float4(0.f, 0.f, 0.f, 0.f);
    float m = -1e30f, l = 0.f;

    const float* base = rnn + (size_t)(chunk * CHUNK) * (B_DIM * H_DIM)
                            + (size_t)b * H_DIM;

    for (int s = 0; s < CHUNK; s++) {
        const float4* row =
            reinterpret_cast<const float4*>(base + (size_t)s * (B_DIM * H_DIM));
        float4 x[8];
#pragma unroll
        for (int j = 0; j < 8; j++) x[j] = row[j * 32 + lane];

        float p = 0.f;
#pragma unroll
        for (int j = 0; j < 8; j++) {
            p += x[j].x * mrg[j].x + x[j].y * mrg[j].y +
                 x[j].z * mrg[j].z + x[j].w * mrg[j].w;
        }
#pragma unroll
        for (int off = 16; off > 0; off >>= 1)
            p += __shfl_xor_sync(0xffffffffu, p, off);

        float mnew  = fmaxf(m, p);
        float scale = __expf(m - mnew);
        float w     = __expf(p - mnew);
#pragma unroll
        for (int j = 0; j < 8; j++) {
            acc[j].x = acc[j].x * scale + w * x[j].x;
            acc[j].y = acc[j].y * scale + w * x[j].y;
            acc[j].z = acc[j].z * scale + w * x[j].z;
            acc[j].w = acc[j].w * scale + w * x[j].w;
        }
        l = l * scale + w;
        m = mnew;
    }

    const int part = b * SPLIT + chunk;
    float4* out4 = reinterpret_cast<float4*>(g_acc + (size_t)part * H_DIM);
#pragma unroll
    for (int j = 0; j < 8; j++) out4[j * 32 + lane] = acc[j];
    if (lane == 0) {
        g_m[part] = m;
        g_l[part] = l;
    }
}

// Fused combine + weighted sum. grid = (16 h-slices, 32 batches), 256 threads.
__global__ __launch_bounds__(256) void pass2(float* __restrict__ out) {
    const int slice = blockIdx.x;        // 0..15
    const int b     = blockIdx.y;        // 0..31
    const int tid   = threadIdx.x;
    const int lane  = tid & 31;
    const int wid   = tid >> 5;

    __shared__ float sw[SPLIT];
    __shared__ float s_red[8];

    // ---- normalized chunk weights (threads 0..SPLIT-1 own one chunk) ----
    float mm = -1e30f, ll = 0.f;
    if (tid < SPLIT) {
        mm = g_m[b * SPLIT + tid];
        ll = g_l[b * SPLIT + tid];
    }
    float v = mm;
#pragma unroll
    for (int off = 16; off > 0; off >>= 1)
        v = fmaxf(v, __shfl_xor_sync(0xffffffffu, v, off));
    if (lane == 0) s_red[wid] = v;
    __syncthreads();
    float M = s_red[0];
#pragma unroll
    for (int k = 1; k < 8; k++) M = fmaxf(M, s_red[k]);
    __syncthreads();

    float e  = (tid < SPLIT) ? __expf(mm - M) : 0.f;
    float le = ll * e;
#pragma unroll
    for (int off = 16; off > 0; off >>= 1)
        le += __shfl_xor_sync(0xffffffffu, le, off);
    if (lane == 0) s_red[wid] = le;
    __syncthreads();
    float L = 0.f;
#pragma unroll
    for (int k = 0; k < 8; k++) L += s_red[k];
    if (tid < SPLIT) sw[tid] = e / L;
    __syncthreads();

    // ---- weighted sum over SPLIT chunks for 64 h values ----
    const int hq = tid & 15;             // 16 float4 = 64 floats per slice
    const int cg = tid >> 4;             // 16 groups x 4 chunks

    const float* bse = g_acc + ((size_t)b * SPLIT) * H_DIM + slice * 64 + hq * 4;

    float rx = 0.f, ry = 0.f, rz = 0.f, rw = 0.f;
#pragma unroll
    for (int k = 0; k < 4; k++) {
        int chunk = k * 16 + cg;
        float4 a = *reinterpret_cast<const float4*>(bse + (size_t)chunk * H_DIM);
        float w = sw[chunk];
        rx += w * a.x; ry += w * a.y; rz += w * a.z; rw += w * a.w;
    }

    __shared__ float4 red[256];
    red[tid] = make_float4(rx, ry, rz, rw);
    __syncthreads();
#pragma unroll
    for (int st = 8; st > 0; st >>= 1) {
        if (cg < st) {
            float4 o = red[tid + 16 * st];
            rx += o.x; ry += o.y; rz += o.z; rw += o.w;
            red[tid] = make_float4(rx, ry, rz, rw);
        }
        __syncthreads();
    }

    if (cg == 0) {
        reinterpret_cast<float4*>(out)[(b * H_DIM + slice * 64) / 4 + hq] =
            make_float4(rx, ry, rz, rw);
    }
}

extern "C" void kernel_launch(void* const* d_in, const int* in_sizes, int n_in,
                              void* d_out, int out_size) {
    const float* rnn   = (const float*)d_in[0];
    const float* state = (const float*)d_in[1];
    float* out         = (float*)d_out;

    pass1<<<NPART / 8, 256>>>(rnn, state);
    dim3 g2(16, B_DIM);
    pass2<<<g2, 256>>>(out);
}

// round 14
// speedup vs baseline: 1.0434x; 1.0434x over previous
#include <cuda_runtime.h>

// DotAttention: rnn_out [S,B,H] f32, state [2,2,B,H/2] f32 -> out [B,H,1] f32
// S=2048, B=32, H=1024.
// pass1: EXACT R7 shape (best measured 42.2us): one warp per (b, 32-row
//        chunk), 256-thr CTAs, register mrg, CTA combine -> 256 partials.
// pass2: max-parallel combine: 256 CTAs x 256 thr, ONE g_acc load per thread,
//        smem tree reduce over the 8 partials.

#define S_LEN 2048
#define B_DIM 32
#define H_DIM 1024
#define SPLIT 64
#define CHUNK (S_LEN / SPLIT)          // 32 rows per warp
#define WARPS_PER_CTA 8
#define NCTA  (B_DIM * SPLIT / WARPS_PER_CTA)   // 256 CTAs
#define PPB   (SPLIT / WARPS_PER_CTA)           // 8 partials per batch

__device__ float g_m[NCTA];
__device__ float g_l[NCTA];
__device__ float g_acc[(size_t)NCTA * H_DIM];   // 1 MB scratch (L2-resident)

__global__ __launch_bounds__(256) void pass1(const float* __restrict__ rnn,
                                             const float* __restrict__ state) {
    const int tid  = threadIdx.x;
    const int lane = tid & 31;
    const int wid  = tid >> 5;
    const int warp  = blockIdx.x * WARPS_PER_CTA + wid;
    const int b     = warp / SPLIT;
    const int chunk = warp % SPLIT;

    // merged[b, h]: h = j*128 + lane*4; direction = h>>9
    float4 mrg[8];
#pragma unroll
    for (int j = 0; j < 8; j++) {
        int h = j * 128 + lane * 4;
        int d = h >> 9;
        int hh = h & 511;
        mrg[j] = *reinterpret_cast<const float4*>(
            state + (size_t)(2 + d) * B_DIM * 512 + (size_t)b * 512 + hh);
    }

    float4 acc[8];
#pragma unroll
    for (int j = 0; j < 8; j++) acc[j] = make_float4(0.f, 0.f, 0.f, 0.f);
    float m = -1e30f, l = 0.f;

    const float* base = rnn + (size_t)(chunk * CHUNK) * (B_DIM * H_DIM)
                            + (size_t)b * H_DIM;

    for (int s = 0; s < CHUNK; s++) {
        const float4* row =
            reinterpret_cast<const float4*>(base + (size_t)s * (B_DIM * H_DIM));
        float4 x[8];
#pragma unroll
        for (int j = 0; j < 8; j++) x[j] = row[j * 32 + lane];

        float p = 0.f;
#pragma unroll
        for (int j = 0; j < 8; j++) {
            p += x[j].x * mrg[j].x + x[j].y * mrg[j].y +
                 x[j].z * mrg[j].z + x[j].w * mrg[j].w;
        }
#pragma unroll
        for (int off = 16; off > 0; off >>= 1)
            p += __shfl_xor_sync(0xffffffffu, p, off);

        float mnew  = fmaxf(m, p);
        float scale = __expf(m - mnew);
        float w     = __expf(p - mnew);
#pragma unroll
        for (int j = 0; j < 8; j++) {
            acc[j].x = acc[j].x * scale + w * x[j].x;
            acc[j].y = acc[j].y * scale + w * x[j].y;
            acc[j].z = acc[j].z * scale + w * x[j].z;
            acc[j].w = acc[j].w * scale + w * x[j].w;
        }
        l = l * scale + w;
        m = mnew;
    }

    // ---- CTA-level combine of the 8 warps' partials ----
    __shared__ float s_m[WARPS_PER_CTA], s_l[WARPS_PER_CTA];
    __shared__ float4 sbuf[WARPS_PER_CTA][256];   // 32 KB

    if (lane == 0) { s_m[wid] = m; s_l[wid] = l; }
    __syncthreads();

    float M = s_m[0];
#pragma unroll
    for (int k = 1; k < WARPS_PER_CTA; k++) M = fmaxf(M, s_m[k]);
    float sc = __expf(m - M);

#pragma unroll
    for (int j = 0; j < 8; j++) {
        sbuf[wid][j * 32 + lane] =
            make_float4(acc[j].x * sc, acc[j].y * sc, acc[j].z * sc, acc[j].w * sc);
    }
    __syncthreads();

    // warp `wid` reduces j-group `wid` across the 8 staged buffers
    float4 r = make_float4(0.f, 0.f, 0.f, 0.f);
#pragma unroll
    for (int k = 0; k < WARPS_PER_CTA; k++) {
        float4 a = sbuf[k][wid * 32 + lane];
        r.x += a.x; r.y += a.y; r.z += a.z; r.w += a.w;
    }

    float4* out4 = reinterpret_cast<float4*>(g_acc + (size_t)blockIdx.x * H_DIM);
    out4[wid * 32 + lane] = r;

    if (tid == 0) {
        float L = 0.f;
#pragma unroll
        for (int k = 0; k < WARPS_PER_CTA; k++)
            L += s_l[k] * __expf(s_m[k] - M);
        g_m[blockIdx.x] = M;
        g_l[blockIdx.x] = L;
    }
}

// Max-parallel combine: grid (8, 32) x 256 thr. Thread (pos, k) loads ONE
// float4 of partial k at h-position pos; smem tree reduce over k.
__global__ __launch_bounds__(256) void pass2(float* __restrict__ out) {
    const int slice = blockIdx.x;        // 0..7 (128 h values each)
    const int b     = blockIdx.y;        // 0..31
    const int tid   = threadIdx.x;
    const int pos   = tid & 31;          // 32 float4 positions in slice
    const int k     = tid >> 5;          // 0..7 partial index

    // per-thread redundant weight computation (broadcast loads)
    float mv[PPB], lv[PPB];
#pragma unroll
    for (int j = 0; j < PPB; j++) {
        mv[j] = g_m[b * PPB + j];
        lv[j] = g_l[b * PPB + j];
    }
    float M = mv[0];
#pragma unroll
    for (int j = 1; j < PPB; j++) M = fmaxf(M, mv[j]);
    float L = 0.f;
#pragma unroll
    for (int j = 0; j < PPB; j++) L += lv[j] * __expf(mv[j] - M);
    float w   = __expf(mv[k] - M);
    float inv = 1.f / L;

    // one load: partial k, h-position slice*128 + pos*4
    float4 a = *reinterpret_cast<const float4*>(
        g_acc + ((size_t)(b * PPB + k)) * H_DIM + slice * 128 + pos * 4);

    __shared__ float4 red[8][32];
    red[k][pos] = make_float4(w * a.x, w * a.y, w * a.z, w * a.w);
    __syncthreads();

#pragma unroll
    for (int st = 4; st > 0; st >>= 1) {
        if (k < st) {
            float4 o = red[k + st][pos];
            float4 c = red[k][pos];
            red[k][pos] = make_float4(c.x + o.x, c.y + o.y, c.z + o.z, c.w + o.w);
        }
        __syncthreads();
    }

    if (k == 0) {
        float4 c = red[0][pos];
        reinterpret_cast<float4*>(out)[(b * H_DIM + slice * 128) / 4 + pos] =
            make_float4(c.x * inv, c.y * inv, c.z * inv, c.w * inv);
    }
}

extern "C" void kernel_launch(void* const* d_in, const int* in_sizes, int n_in,
                              void* d_out, int out_size) {
    const float* rnn   = (const float*)d_in[0];
    const float* state = (const float*)d_in[1];
    float* out         = (float*)d_out;

    pass1<<<NCTA, 256>>>(rnn, state);
    dim3 g2(8, B_DIM);
    pass2<<<g2, 256>>>(out);
}